// round 2
// baseline (speedup 1.0000x reference)
#include <cuda_runtime.h>
#include <cuda_bf16.h>
#include <math_constants.h>

// Problem: B=256, N=256, K=16, DIM=128
//   gated[b,n,k,:] = extra[b,n,:] * neighbor[b,n,k,:]
//   z = gated @ w1[:128] + weight[...,None]*w1[128]       [16,128] per (b,n)
//   z = leaky_relu(z, 0.2)
//   a[k] = z @ w2                                          [16]
//   a = softmax(a)  (over K)
//   out[b,n,:] = sum_k a[k] * neighbor[b,n,k,:]
//
// Inputs (metadata order):
//  0: self_vectors  [B,N,128]  f32   (UNUSED)
//  1: neighbor      [B,N,16,128] f32
//  2: batch_size    (scalar)         (UNUSED)
//  3: masks         [B,N] i32        (UNUSED)
//  4: neighbor_weight [B,N,16] f32
//  5: extra         [B,N,128] f32
//  6: w_1           [129,128] f32
//  7: w_2           [128,1]  f32
// out: [B,N,128] f32

#define DIMX    128
#define KN      16
#define GROUP   16
#define NTHREADS 256

// shared layout (floats):
//  w1s   : 129*128 = 16512   (rows 0..127 = W, row 128 = bias row)
//  w2s   : 128
//  nb    : 16*128  = 2048    (raw neighbor tile)
//  gt    : 16*128  = 2048    (gated tile)
//  exs   : 128
//  wts   : 16
//  sal   : 16
#define SM_W1   0
#define SM_W2   (129*128)
#define SM_NB   (SM_W2 + 128)
#define SM_GT   (SM_NB + KN*DIMX)
#define SM_EX   (SM_GT + KN*DIMX)
#define SM_WT   (SM_EX + DIMX)
#define SM_AL   (SM_WT + KN)
#define SM_FLOATS (SM_AL + KN)

__device__ __forceinline__ float leaky02(float v) {
    return v > 0.0f ? v : 0.2f * v;
}

extern "C" __global__ void __launch_bounds__(NTHREADS)
agg_kernel(const float* __restrict__ neighbor,
           const float* __restrict__ nweight,
           const float* __restrict__ extra,
           const float* __restrict__ w1,
           const float* __restrict__ w2,
           float* __restrict__ out,
           int total_bn)
{
    extern __shared__ float sm[];
    float* w1s = sm + SM_W1;
    float* w2s = sm + SM_W2;
    float* nb  = sm + SM_NB;
    float* gt  = sm + SM_GT;
    float* exs = sm + SM_EX;
    float* wts = sm + SM_WT;
    float* sal = sm + SM_AL;

    const int tid  = threadIdx.x;
    const int warp = tid >> 5;
    const int lane = tid & 31;

    // ---- load weights once per block ----
    {
        const float4* src = (const float4*)w1;
        float4* dst = (float4*)w1s;
        for (int i = tid; i < (129 * DIMX) / 4; i += NTHREADS) dst[i] = src[i];
        if (tid < DIMX / 4) ((float4*)w2s)[tid] = ((const float4*)w2)[tid];
    }
    __syncthreads();

    const int bn0 = blockIdx.x * GROUP;

    for (int g = 0; g < GROUP; ++g) {
        const int bn = bn0 + g;
        if (bn >= total_bn) break;

        // ---- load per-(b,n) tiles ----
        {
            const float4* nsrc = (const float4*)(neighbor + (size_t)bn * KN * DIMX);
            float4* ndst = (float4*)nb;
            #pragma unroll
            for (int i = tid; i < (KN * DIMX) / 4; i += NTHREADS) ndst[i] = nsrc[i];
            if (tid < DIMX / 4)
                ((float4*)exs)[tid] = ((const float4*)(extra + (size_t)bn * DIMX))[tid];
            if (tid < KN)
                wts[tid] = nweight[(size_t)bn * KN + tid];
        }
        __syncthreads();

        // ---- gated tile ----
        #pragma unroll
        for (int i = tid; i < KN * DIMX; i += NTHREADS)
            gt[i] = nb[i] * exs[i & (DIMX - 1)];
        __syncthreads();

        // ---- z = gated @ W + bias ; leaky ; dot w2 ----
        // warp w handles k0=2w, k1=2w+1 ; lane handles e = 4*lane .. 4*lane+3
        const int k0 = warp * 2;
        const int k1 = k0 + 1;
        const float* g0p = gt + k0 * DIMX;
        const float* g1p = gt + k1 * DIMX;

        float4 z0 = make_float4(0.f, 0.f, 0.f, 0.f);
        float4 z1 = make_float4(0.f, 0.f, 0.f, 0.f);

        #pragma unroll 8
        for (int d = 0; d < DIMX; ++d) {
            const float4 w = ((const float4*)(w1s + d * DIMX))[lane];
            const float a0 = g0p[d];
            const float a1 = g1p[d];
            z0.x = fmaf(a0, w.x, z0.x);
            z0.y = fmaf(a0, w.y, z0.y);
            z0.z = fmaf(a0, w.z, z0.z);
            z0.w = fmaf(a0, w.w, z0.w);
            z1.x = fmaf(a1, w.x, z1.x);
            z1.y = fmaf(a1, w.y, z1.y);
            z1.z = fmaf(a1, w.z, z1.z);
            z1.w = fmaf(a1, w.w, z1.w);
        }

        // bias row (w1[128]) scaled by neighbor_weight
        {
            const float4 b = ((const float4*)(w1s + 128 * DIMX))[lane];
            const float wk0 = wts[k0];
            const float wk1 = wts[k1];
            z0.x = fmaf(wk0, b.x, z0.x);
            z0.y = fmaf(wk0, b.y, z0.y);
            z0.z = fmaf(wk0, b.z, z0.z);
            z0.w = fmaf(wk0, b.w, z0.w);
            z1.x = fmaf(wk1, b.x, z1.x);
            z1.y = fmaf(wk1, b.y, z1.y);
            z1.z = fmaf(wk1, b.z, z1.z);
            z1.w = fmaf(wk1, b.w, z1.w);
        }

        // leaky relu + dot with w2 (partial over this lane's 4 e's)
        float p0, p1;
        {
            const float4 v2 = ((const float4*)w2s)[lane];
            p0 = leaky02(z0.x) * v2.x + leaky02(z0.y) * v2.y +
                 leaky02(z0.z) * v2.z + leaky02(z0.w) * v2.w;
            p1 = leaky02(z1.x) * v2.x + leaky02(z1.y) * v2.y +
                 leaky02(z1.z) * v2.z + leaky02(z1.w) * v2.w;
        }

        // warp reduce over 32 lanes
        #pragma unroll
        for (int off = 16; off > 0; off >>= 1) {
            p0 += __shfl_xor_sync(0xffffffffu, p0, off);
            p1 += __shfl_xor_sync(0xffffffffu, p1, off);
        }
        if (lane == 0) { sal[k0] = p0; sal[k1] = p1; }
        __syncthreads();

        // ---- softmax over K=16 (warp 0) ----
        if (warp == 0) {
            float v = (lane < KN) ? sal[lane] : -CUDART_INF_F;
            float m = v;
            #pragma unroll
            for (int off = 16; off > 0; off >>= 1)
                m = fmaxf(m, __shfl_xor_sync(0xffffffffu, m, off));
            float ev = (lane < KN) ? __expf(v - m) : 0.f;
            float s = ev;
            #pragma unroll
            for (int off = 16; off > 0; off >>= 1)
                s += __shfl_xor_sync(0xffffffffu, s, off);
            if (lane < KN) sal[lane] = ev / s;
        }
        __syncthreads();

        // ---- output: out[d] = sum_k alpha[k] * nb[k][d] ----
        if (tid < DIMX) {
            float acc = 0.f;
            #pragma unroll
            for (int k = 0; k < KN; ++k)
                acc = fmaf(sal[k], nb[k * DIMX + tid], acc);
            out[(size_t)bn * DIMX + tid] = acc;
        }
        __syncthreads();
    }
}

extern "C" void kernel_launch(void* const* d_in, const int* in_sizes, int n_in,
                              void* d_out, int out_size) {
    const float* neighbor = (const float*)d_in[1];
    const float* nweight  = (const float*)d_in[4];
    const float* extra    = (const float*)d_in[5];
    const float* w1       = (const float*)d_in[6];
    const float* w2       = (const float*)d_in[7];
    float* out            = (float*)d_out;

    const int total_bn = in_sizes[5] / DIMX;   // extra_vector element count / DIM
    const int nblocks  = (total_bn + GROUP - 1) / GROUP;
    const size_t smem_bytes = (size_t)SM_FLOATS * sizeof(float);

    static bool attr_set = false;
    // idempotent, cheap; safe to call every launch (not a stream op)
    cudaFuncSetAttribute(agg_kernel, cudaFuncAttributeMaxDynamicSharedMemorySize,
                         (int)smem_bytes);
    (void)attr_set;

    agg_kernel<<<nblocks, NTHREADS, smem_bytes>>>(neighbor, nweight, extra,
                                                  w1, w2, out, total_bn);
}

// round 4
// speedup vs baseline: 4.0316x; 4.0316x over previous
#include <cuda_runtime.h>
#include <cuda_bf16.h>
#include <cstdint>

// GlobalAggregator: B=256, N=256, K=16, DIM=128
// Tile = 8 (b,n) pairs -> M=128 rows (m = bnl*16 + k).
//   A[m][d] = extra[bn][d] * neighbor[bn][k][d]   (bf16 hi/lo split)
//   Bt[e][d] = w1[d][e]                           (bf16 hi/lo, built once per block)
//   D = A @ Bt^T via mma.sync bf16 x3 (hi*hi + hi*lo + lo*hi), fp32 accum
//   epilogue per warp (1 bn pair): z=D+wk*bias; leaky; dot w2; softmax(16); out=sum alpha*nb

#define DIMX 128
#define KN   16
#define TBN  8
#define MROWS 128
#define NTHREADS 256
#define ASTRIDE 272          // bytes per row (128 bf16 + 8 pad)

#define SM_A1   0
#define SM_A2   34816
#define SM_B1   69632
#define SM_B2   104448
#define SM_NB   139264       // 128x128 f32
#define SM_BIAS 204800       // 128 f32
#define SM_W2   205312
#define SM_WT   205824
#define SM_AL   206336
#define SM_TOTAL 206848

static __device__ __forceinline__ uint32_t smem_u32(const void* p) {
    uint32_t a;
    asm("{ .reg .u64 t; cvta.to.shared.u64 t, %1; cvt.u32.u64 %0, t; }" : "=r"(a) : "l"(p));
    return a;
}
static __device__ __forceinline__ void ldsm4(uint32_t& r0, uint32_t& r1, uint32_t& r2, uint32_t& r3,
                                             uint32_t addr) {
    asm volatile("ldmatrix.sync.aligned.m8n8.x4.shared.b16 {%0,%1,%2,%3}, [%4];"
                 : "=r"(r0), "=r"(r1), "=r"(r2), "=r"(r3) : "r"(addr));
}
static __device__ __forceinline__ void mma_bf16(float& c0, float& c1, float& c2, float& c3,
                                                uint32_t a0, uint32_t a1, uint32_t a2, uint32_t a3,
                                                uint32_t b0, uint32_t b1) {
    asm volatile("mma.sync.aligned.m16n8k16.row.col.f32.bf16.bf16.f32 "
                 "{%0,%1,%2,%3},{%4,%5,%6,%7},{%8,%9},{%0,%1,%2,%3};"
                 : "+f"(c0), "+f"(c1), "+f"(c2), "+f"(c3)
                 : "r"(a0), "r"(a1), "r"(a2), "r"(a3), "r"(b0), "r"(b1));
}
__device__ __forceinline__ float leaky02(float v) { return v > 0.0f ? v : 0.2f * v; }

extern "C" __global__ void __launch_bounds__(NTHREADS, 1)
agg_mma_kernel(const float* __restrict__ neighbor,
               const float* __restrict__ nweight,
               const float* __restrict__ extra,
               const float* __restrict__ w1,
               const float* __restrict__ w2,
               float* __restrict__ out,
               int ntiles)
{
    extern __shared__ __align__(16) char smem[];
    const uint32_t sbase = smem_u32(smem);
    const int tid  = threadIdx.x;
    const int warp = tid >> 5;
    const int lane = tid & 31;

    float* nbf   = (float*)(smem + SM_NB);
    float* biass = (float*)(smem + SM_BIAS);
    float* w2s   = (float*)(smem + SM_W2);
    float* wtile = (float*)(smem + SM_WT);
    float* sal   = (float*)(smem + SM_AL);

    // ---- build Bt (w1 transposed) hi/lo once per block ----
    for (int idx = tid; idx < DIMX * DIMX; idx += NTHREADS) {
        int d = idx >> 7;          // reduction dim (w1 row)
        int e = idx & 127;         // output dim  (w1 col) -> Bt row
        float v = w1[idx];
        __nv_bfloat16 hb = __float2bfloat16(v);
        float lo = v - __bfloat162float(hb);
        __nv_bfloat16 lb = __float2bfloat16(lo);
        uint32_t off = (uint32_t)e * ASTRIDE + (uint32_t)d * 2;
        *(__nv_bfloat16*)(smem + SM_B1 + off) = hb;
        *(__nv_bfloat16*)(smem + SM_B2 + off) = lb;
    }
    if (tid < DIMX) {
        biass[tid] = w1[DIMX * DIMX + tid];
        w2s[tid]   = w2[tid];
    }
    __syncthreads();

    // per-lane ldmatrix base offsets
    // A frag: rows 16*warp + (lane&7) + ((lane>>3)&1)*8 ; col-16B sel = lane>>4
    const uint32_t a_row = 16 * warp + (lane & 7) + ((lane >> 3) & 1) * 8;
    const uint32_t a_base = sbase + a_row * ASTRIDE + (lane >> 4) * 16;
    // B frag: rows n0 + (lane&7) + (lane>=16)*8 ; col-16B sel = (lane>>3)&1
    const uint32_t b_row8 = (lane & 7) + ((lane >> 4) & 1) * 8;
    const uint32_t b_base = sbase + b_row8 * ASTRIDE + ((lane >> 3) & 1) * 16;

    for (int tile = blockIdx.x; tile < ntiles; tile += gridDim.x) {
        const size_t bn0 = (size_t)tile * TBN;

        // ---- load tile: raw neighbor fp32 + gated bf16 hi/lo ----
        if (tid < MROWS) wtile[tid] = nweight[bn0 * KN + tid];
        {
            const float4* nsrc = (const float4*)neighbor + (size_t)tile * 4096;
            const float4* esrc = (const float4*)extra + bn0 * 32;
            float4* nraw = (float4*)nbf;
            #pragma unroll
            for (int i = 0; i < 16; ++i) {
                int idx4 = tid + i * NTHREADS;      // 0..4095
                int m  = idx4 >> 5;
                int q  = idx4 & 31;                 // float4 index within row
                float4 nv = nsrc[idx4];
                nraw[idx4] = nv;
                float4 ev = __ldg(esrc + (m >> 4) * 32 + q);
                float g0 = nv.x * ev.x, g1 = nv.y * ev.y, g2 = nv.z * ev.z, g3 = nv.w * ev.w;

                __nv_bfloat16 h0 = __float2bfloat16(g0), h1 = __float2bfloat16(g1);
                __nv_bfloat16 h2 = __float2bfloat16(g2), h3 = __float2bfloat16(g3);
                __nv_bfloat16 l0 = __float2bfloat16(g0 - __bfloat162float(h0));
                __nv_bfloat16 l1 = __float2bfloat16(g1 - __bfloat162float(h1));
                __nv_bfloat16 l2 = __float2bfloat16(g2 - __bfloat162float(h2));
                __nv_bfloat16 l3 = __float2bfloat16(g3 - __bfloat162float(h3));

                __nv_bfloat162 hA(h0, h1), hB(h2, h3), lA(l0, l1), lB(l2, l3);
                uint2 hv, lv;
                hv.x = *(uint32_t*)&hA; hv.y = *(uint32_t*)&hB;
                lv.x = *(uint32_t*)&lA; lv.y = *(uint32_t*)&lB;

                uint32_t off = (uint32_t)m * ASTRIDE + (uint32_t)q * 8;
                *(uint2*)(smem + SM_A1 + off) = hv;
                *(uint2*)(smem + SM_A2 + off) = lv;
            }
        }
        __syncthreads();

        // ---- GEMM: C[16 m-rows][128 e] per warp ----
        float c[16][4];
        #pragma unroll
        for (int nt = 0; nt < 16; ++nt) { c[nt][0]=0.f; c[nt][1]=0.f; c[nt][2]=0.f; c[nt][3]=0.f; }

        #pragma unroll
        for (int kc = 0; kc < 8; ++kc) {
            uint32_t ah0, ah1, ah2, ah3, al0, al1, al2, al3;
            ldsm4(ah0, ah1, ah2, ah3, a_base + SM_A1 + kc * 32);
            ldsm4(al0, al1, al2, al3, a_base + SM_A2 + kc * 32);
            #pragma unroll
            for (int np = 0; np < 8; ++np) {        // pair of n-tiles
                uint32_t bh0, bh1, bh2, bh3, bl0, bl1, bl2, bl3;
                uint32_t boff = (uint32_t)(np * 16) * ASTRIDE + kc * 32;
                ldsm4(bh0, bh1, bh2, bh3, b_base + SM_B1 + boff);
                ldsm4(bl0, bl1, bl2, bl3, b_base + SM_B2 + boff);
                float* cA = c[2 * np];
                float* cB = c[2 * np + 1];
                mma_bf16(cA[0], cA[1], cA[2], cA[3], ah0, ah1, ah2, ah3, bh0, bh1);
                mma_bf16(cB[0], cB[1], cB[2], cB[3], ah0, ah1, ah2, ah3, bh2, bh3);
                mma_bf16(cA[0], cA[1], cA[2], cA[3], ah0, ah1, ah2, ah3, bl0, bl1);
                mma_bf16(cB[0], cB[1], cB[2], cB[3], ah0, ah1, ah2, ah3, bl2, bl3);
                mma_bf16(cA[0], cA[1], cA[2], cA[3], al0, al1, al2, al3, bh0, bh1);
                mma_bf16(cB[0], cB[1], cB[2], cB[3], al0, al1, al2, al3, bh2, bh3);
            }
        }

        // ---- epilogue (warp-local, bn = bn0 + warp) ----
        const int g = lane >> 2;            // k row 0..7 (also k+8)
        const int i2 = (lane & 3) * 2;
        const float wk0 = wtile[warp * 16 + g];
        const float wk1 = wtile[warp * 16 + g + 8];

        float p0 = 0.f, p1 = 0.f;
        #pragma unroll
        for (int nt = 0; nt < 16; ++nt) {
            int e0 = nt * 8 + i2;
            int e1 = e0 + 1;
            float b0 = biass[e0], b1 = biass[e1];
            float v0 = w2s[e0], v1 = w2s[e1];
            p0 = fmaf(leaky02(c[nt][0] + wk0 * b0), v0, p0);
            p0 = fmaf(leaky02(c[nt][1] + wk0 * b1), v1, p0);
            p1 = fmaf(leaky02(c[nt][2] + wk1 * b0), v0, p1);
            p1 = fmaf(leaky02(c[nt][3] + wk1 * b1), v1, p1);
        }
        // reduce over the 4 lanes of each row-quad
        p0 += __shfl_xor_sync(0xffffffffu, p0, 1);
        p0 += __shfl_xor_sync(0xffffffffu, p0, 2);
        p1 += __shfl_xor_sync(0xffffffffu, p1, 1);
        p1 += __shfl_xor_sync(0xffffffffu, p1, 2);

        // softmax over 16 k (v0 at k=g, v1 at k=g+8); duplicates within quads ok
        float mx = fmaxf(p0, p1);
        #pragma unroll
        for (int o = 4; o <= 16; o <<= 1)
            mx = fmaxf(mx, __shfl_xor_sync(0xffffffffu, mx, o));
        float e0v = __expf(p0 - mx);
        float e1v = __expf(p1 - mx);
        float s = e0v + e1v;
        #pragma unroll
        for (int o = 4; o <= 16; o <<= 1)
            s += __shfl_xor_sync(0xffffffffu, s, o);
        if ((lane & 3) == 0) {
            sal[warp * 16 + g]     = e0v / s;
            sal[warp * 16 + g + 8] = e1v / s;
        }
        __syncwarp();

        // ---- out[bn][d] = sum_k alpha[k] * neighbor[bn][k][d] ----
        {
            float al[KN];
            #pragma unroll
            for (int k = 0; k < KN; ++k) al[k] = sal[warp * 16 + k];
            const float4* nb4 = (const float4*)nbf + warp * 16 * 32 + lane;
            float4 acc = make_float4(0.f, 0.f, 0.f, 0.f);
            #pragma unroll
            for (int k = 0; k < KN; ++k) {
                float4 nv = nb4[k * 32];
                acc.x = fmaf(al[k], nv.x, acc.x);
                acc.y = fmaf(al[k], nv.y, acc.y);
                acc.z = fmaf(al[k], nv.z, acc.z);
                acc.w = fmaf(al[k], nv.w, acc.w);
            }
            ((float4*)(out + (bn0 + warp) * DIMX))[lane] = acc;
        }
        __syncthreads();   // protect A tiles / nb before next tile
    }
}

extern "C" void kernel_launch(void* const* d_in, const int* in_sizes, int n_in,
                              void* d_out, int out_size) {
    const float* neighbor = (const float*)d_in[1];
    const float* nweight  = (const float*)d_in[4];
    const float* extra    = (const float*)d_in[5];
    const float* w1       = (const float*)d_in[6];
    const float* w2       = (const float*)d_in[7];
    float* out            = (float*)d_out;

    const int total_bn = in_sizes[5] / DIMX;
    const int ntiles   = total_bn / TBN;

    cudaFuncSetAttribute(agg_mma_kernel, cudaFuncAttributeMaxDynamicSharedMemorySize, SM_TOTAL);
    agg_mma_kernel<<<152, NTHREADS, SM_TOTAL>>>(neighbor, nweight, extra, w1, w2, out, ntiles);
}

// round 5
// speedup vs baseline: 5.6213x; 1.3943x over previous
#include <cuda_runtime.h>
#include <cuda_bf16.h>
#include <cstdint>

// GlobalAggregator: B=256, N=256, K=16, DIM=128
// Fully warp-independent: each warp owns one (b,n) pair at a time.
//   A[16x128] = extra[bn] * neighbor[bn]  -> bf16 hi/lo frags built in registers from global
//   Bt[e][d] = w1[d][e] hi/lo in SMEM (built once per block), read via ldmatrix
//   D = A @ Bt^T via mma.sync bf16 x3 (hi*hi + hi*lo + lo*hi), fp32 accum
//   epilogue warp-local: z=D+wk*bias; leaky(0.2); dot w2 (quad shfl); softmax over 16 (shfl);
//   out = sum_k alpha_k * neighbor[bn][k][:]  (neighbor re-read, L2-resident)

#define DIMX 128
#define KN   16
#define NTHREADS 256
#define BSTRIDE 272          // bytes per Bt row (128 bf16 + 8 pad) -> conflict-free ldmatrix

#define SM_B1   0            // 128 x 272 = 34816
#define SM_B2   34816
#define SM_BIAS 69632        // 128 f32
#define SM_W2   70144        // 128 f32
#define SM_TOTAL 70656

static __device__ __forceinline__ uint32_t smem_u32(const void* p) {
    uint32_t a;
    asm("{ .reg .u64 t; cvta.to.shared.u64 t, %1; cvt.u32.u64 %0, t; }" : "=r"(a) : "l"(p));
    return a;
}
static __device__ __forceinline__ void ldsm4(uint32_t& r0, uint32_t& r1, uint32_t& r2, uint32_t& r3,
                                             uint32_t addr) {
    asm volatile("ldmatrix.sync.aligned.m8n8.x4.shared.b16 {%0,%1,%2,%3}, [%4];"
                 : "=r"(r0), "=r"(r1), "=r"(r2), "=r"(r3) : "r"(addr));
}
static __device__ __forceinline__ void mma_bf16(float& c0, float& c1, float& c2, float& c3,
                                                uint32_t a0, uint32_t a1, uint32_t a2, uint32_t a3,
                                                uint32_t b0, uint32_t b1) {
    asm volatile("mma.sync.aligned.m16n8k16.row.col.f32.bf16.bf16.f32 "
                 "{%0,%1,%2,%3},{%4,%5,%6,%7},{%8,%9},{%0,%1,%2,%3};"
                 : "+f"(c0), "+f"(c1), "+f"(c2), "+f"(c3)
                 : "r"(a0), "r"(a1), "r"(a2), "r"(a3), "r"(b0), "r"(b1));
}
static __device__ __forceinline__ uint32_t pack_hi(float x, float y) {
    __nv_bfloat162 h(__float2bfloat16(x), __float2bfloat16(y));
    return *(uint32_t*)&h;
}
static __device__ __forceinline__ uint32_t pack_lo(float x, float y, uint32_t hi) {
    __nv_bfloat162 h = *(__nv_bfloat162*)&hi;
    __nv_bfloat162 l(__float2bfloat16(x - __bfloat162float(h.x)),
                     __float2bfloat16(y - __bfloat162float(h.y)));
    return *(uint32_t*)&l;
}
__device__ __forceinline__ float leaky02(float v) { return v > 0.0f ? v : 0.2f * v; }

extern "C" __global__ void __launch_bounds__(NTHREADS, 2)
agg_mma_kernel(const float* __restrict__ neighbor,
               const float* __restrict__ nweight,
               const float* __restrict__ extra,
               const float* __restrict__ w1,
               const float* __restrict__ w2,
               float* __restrict__ out,
               int total_bn)
{
    extern __shared__ __align__(16) char smem[];
    const uint32_t sbase = smem_u32(smem);
    const int tid  = threadIdx.x;
    const int warp = tid >> 5;
    const int lane = tid & 31;

    float* biass = (float*)(smem + SM_BIAS);
    float* w2s   = (float*)(smem + SM_W2);

    // ---- build Bt (w1 transposed) hi/lo once per block ----
    for (int idx = tid; idx < DIMX * DIMX; idx += NTHREADS) {
        int d = idx >> 7;          // reduction dim (w1 row)
        int e = idx & 127;         // output dim  (w1 col) -> Bt row
        float v = w1[idx];
        __nv_bfloat16 hb = __float2bfloat16(v);
        __nv_bfloat16 lb = __float2bfloat16(v - __bfloat162float(hb));
        uint32_t off = (uint32_t)e * BSTRIDE + (uint32_t)d * 2;
        *(__nv_bfloat16*)(smem + SM_B1 + off) = hb;
        *(__nv_bfloat16*)(smem + SM_B2 + off) = lb;
    }
    if (tid < DIMX) {
        biass[tid] = w1[DIMX * DIMX + tid];
        w2s[tid]   = w2[tid];
    }
    __syncthreads();

    // B ldmatrix lane addressing: rows (lane&7)+((lane>>4)&1)*8, 16B col sel (lane>>3)&1
    const uint32_t b_base = sbase + ((lane & 7) + ((lane >> 4) & 1) * 8) * BSTRIDE
                          + ((lane >> 3) & 1) * 16;

    const int g  = lane >> 2;          // row group 0..7
    const int i2 = (lane & 3) * 2;     // col pair base

    const int gwarp   = blockIdx.x * 8 + warp;
    const int gstride = gridDim.x * 8;

    for (int bn = gwarp; bn < total_bn; bn += gstride) {
        const float* nbase = neighbor + (size_t)bn * (KN * DIMX);
        const float* ebase = extra + (size_t)bn * DIMX;

        // ---- GEMM: C[16 k-rows][128 e], A frags straight from global ----
        float c[16][4];
        #pragma unroll
        for (int nt = 0; nt < 16; ++nt) { c[nt][0]=0.f; c[nt][1]=0.f; c[nt][2]=0.f; c[nt][3]=0.f; }

        #pragma unroll
        for (int kc = 0; kc < 8; ++kc) {
            const int c0 = kc * 16 + i2;
            // neighbor elements for this lane's A fragment
            float2 n00 = *(const float2*)(nbase + g * DIMX + c0);
            float2 n10 = *(const float2*)(nbase + (g + 8) * DIMX + c0);
            float2 n01 = *(const float2*)(nbase + g * DIMX + c0 + 8);
            float2 n11 = *(const float2*)(nbase + (g + 8) * DIMX + c0 + 8);
            float2 e0  = *(const float2*)(ebase + c0);
            float2 e1  = *(const float2*)(ebase + c0 + 8);

            float g00x = n00.x * e0.x, g00y = n00.y * e0.y;
            float g10x = n10.x * e0.x, g10y = n10.y * e0.y;
            float g01x = n01.x * e1.x, g01y = n01.y * e1.y;
            float g11x = n11.x * e1.x, g11y = n11.y * e1.y;

            uint32_t ah0 = pack_hi(g00x, g00y), ah1 = pack_hi(g10x, g10y);
            uint32_t ah2 = pack_hi(g01x, g01y), ah3 = pack_hi(g11x, g11y);
            uint32_t al0 = pack_lo(g00x, g00y, ah0), al1 = pack_lo(g10x, g10y, ah1);
            uint32_t al2 = pack_lo(g01x, g01y, ah2), al3 = pack_lo(g11x, g11y, ah3);

            #pragma unroll
            for (int np = 0; np < 8; ++np) {       // two 8-wide n-tiles per iter
                uint32_t bh0, bh1, bh2, bh3, bl0, bl1, bl2, bl3;
                uint32_t boff = (uint32_t)(np * 16) * BSTRIDE + kc * 32;
                ldsm4(bh0, bh1, bh2, bh3, b_base + SM_B1 + boff);
                ldsm4(bl0, bl1, bl2, bl3, b_base + SM_B2 + boff);
                float* cA = c[2 * np];
                float* cB = c[2 * np + 1];
                mma_bf16(cA[0], cA[1], cA[2], cA[3], ah0, ah1, ah2, ah3, bh0, bh1);
                mma_bf16(cB[0], cB[1], cB[2], cB[3], ah0, ah1, ah2, ah3, bh2, bh3);
                mma_bf16(cA[0], cA[1], cA[2], cA[3], ah0, ah1, ah2, ah3, bl0, bl1);
                mma_bf16(cB[0], cB[1], cB[2], cB[3], ah0, ah1, ah2, ah3, bl2, bl3);
                mma_bf16(cA[0], cA[1], cA[2], cA[3], al0, al1, al2, al3, bh0, bh1);
                mma_bf16(cB[0], cB[1], cB[2], cB[3], al0, al1, al2, al3, bh2, bh3);
            }
        }

        // ---- epilogue (warp-local) ----
        const float wk0 = nweight[(size_t)bn * KN + g];
        const float wk1 = nweight[(size_t)bn * KN + g + 8];

        float p0 = 0.f, p1 = 0.f;
        #pragma unroll
        for (int nt = 0; nt < 16; ++nt) {
            int e0i = nt * 8 + i2;
            float b0 = biass[e0i], b1 = biass[e0i + 1];
            float v0 = w2s[e0i],  v1 = w2s[e0i + 1];
            p0 = fmaf(leaky02(c[nt][0] + wk0 * b0), v0, p0);
            p0 = fmaf(leaky02(c[nt][1] + wk0 * b1), v1, p0);
            p1 = fmaf(leaky02(c[nt][2] + wk1 * b0), v0, p1);
            p1 = fmaf(leaky02(c[nt][3] + wk1 * b1), v1, p1);
        }
        p0 += __shfl_xor_sync(0xffffffffu, p0, 1);
        p0 += __shfl_xor_sync(0xffffffffu, p0, 2);
        p1 += __shfl_xor_sync(0xffffffffu, p1, 1);
        p1 += __shfl_xor_sync(0xffffffffu, p1, 2);

        // softmax over 16 k (k=g in p0, k=g+8 in p1); dup within quads is fine
        float mx = fmaxf(p0, p1);
        #pragma unroll
        for (int o = 4; o <= 16; o <<= 1)
            mx = fmaxf(mx, __shfl_xor_sync(0xffffffffu, mx, o));
        float e0v = __expf(p0 - mx);
        float e1v = __expf(p1 - mx);
        float s = e0v + e1v;
        #pragma unroll
        for (int o = 4; o <= 16; o <<= 1)
            s += __shfl_xor_sync(0xffffffffu, s, o);
        float a0n = e0v / s;
        float a1n = e1v / s;

        // broadcast alpha[k] via shfl (source lane 4*(k&7))
        float al[KN];
        #pragma unroll
        for (int k = 0; k < 8; ++k)  al[k]     = __shfl_sync(0xffffffffu, a0n, k << 2);
        #pragma unroll
        for (int k = 0; k < 8; ++k)  al[k + 8] = __shfl_sync(0xffffffffu, a1n, k << 2);

        // ---- out[bn][d] = sum_k alpha[k] * neighbor[bn][k][d]  (re-read, L2 hot) ----
        {
            const float4* nb4 = (const float4*)nbase + lane;
            float4 acc = make_float4(0.f, 0.f, 0.f, 0.f);
            #pragma unroll
            for (int k = 0; k < KN; ++k) {
                float4 nv = nb4[k * 32];
                acc.x = fmaf(al[k], nv.x, acc.x);
                acc.y = fmaf(al[k], nv.y, acc.y);
                acc.z = fmaf(al[k], nv.z, acc.z);
                acc.w = fmaf(al[k], nv.w, acc.w);
            }
            ((float4*)(out + (size_t)bn * DIMX))[lane] = acc;
        }
    }
}

extern "C" void kernel_launch(void* const* d_in, const int* in_sizes, int n_in,
                              void* d_out, int out_size) {
    const float* neighbor = (const float*)d_in[1];
    const float* nweight  = (const float*)d_in[4];
    const float* extra    = (const float*)d_in[5];
    const float* w1       = (const float*)d_in[6];
    const float* w2       = (const float*)d_in[7];
    float* out            = (float*)d_out;

    const int total_bn = in_sizes[5] / DIMX;   // 65536

    cudaFuncSetAttribute(agg_mma_kernel, cudaFuncAttributeMaxDynamicSharedMemorySize, SM_TOTAL);
    agg_mma_kernel<<<304, NTHREADS, SM_TOTAL>>>(neighbor, nweight, extra, w1, w2, out, total_bn);
}